// round 14
// baseline (speedup 1.0000x reference)
#include <cuda_runtime.h>
#include <cuda_bf16.h>
#include <cstdint>
#include <cstring>

#define D_IN      512
#define NUM_CODES 2048
#define D_OUT     256
#define MAX_ROWS  100096   // ceil(100000/128)*128

typedef unsigned long long u64;

// Scratch (no allocations allowed -> __device__ globals, zero-initialized)
__device__ float g_h[(size_t)MAX_ROWS * D_IN];            // projected features (exact fp32)
__device__ __nv_bfloat16 g_hb[(size_t)MAX_ROWS * D_IN];   // bf16 copy of h
__device__ __nv_bfloat16 g_cbb[(size_t)NUM_CODES * D_IN]; // bf16 codebook
__device__ float g_hsq[MAX_ROWS];                         // fl32(||h||^2)
__device__ float g_proj[(size_t)NUM_CODES * D_OUT];       // 0.25 * codebook @ head_w
__device__ float g_cbsq[NUM_CODES];                       // fl32(||codebook_c||^2)
__device__ int   g_cand[(size_t)MAX_ROWS * 16];           // 16 candidates per row

#define LDSM4(r0,r1,r2,r3,addr) \
    asm volatile("ldmatrix.sync.aligned.m8n8.x4.shared.b16 {%0,%1,%2,%3},[%4];" \
        : "=r"(r0), "=r"(r1), "=r"(r2), "=r"(r3) : "r"(addr))

#define MMA16816(d, a, b) \
    asm volatile("mma.sync.aligned.m16n8k16.row.col.f32.bf16.bf16.f32 " \
        "{%0,%1,%2,%3},{%4,%5,%6,%7},{%8,%9},{%0,%1,%2,%3};" \
        : "+f"((d)[0]), "+f"((d)[1]), "+f"((d)[2]), "+f"((d)[3]) \
        : "r"((a)[0]), "r"((a)[1]), "r"((a)[2]), "r"((a)[3]), "r"((b)[0]), "r"((b)[1]))

__device__ __forceinline__ unsigned bf2u(__nv_bfloat162 v) {
    unsigned u; memcpy(&u, &v, 4); return u;
}

// ---------------------------------------------------------------------------
// Kernel 1: h = x @ linear_proj   (M x 512) @ (512 x 512)
// EXACT bits: single fp32 accumulator per element, __fmaf_rn, k strictly
// ascending. Tile 128x128, BK=32, 256 threads, 8x8/thread (R11-validated).
// Epilogue also emits bf16 h for the approximate pass.
// ---------------------------------------------------------------------------
__global__ __launch_bounds__(256, 2) void k_gemm_xw(
    const float* __restrict__ A, const float* __restrict__ B, int M)
{
    __shared__ float sA[32][132];   // [k][m]
    __shared__ float sB[32][132];   // [k][n]

    const int tid = threadIdx.x;
    const int tx = tid & 15, ty = tid >> 4;
    const int row0 = blockIdx.x * 128;
    const int col0 = blockIdx.y * 128;

    float acc[8][8];
#pragma unroll
    for (int i = 0; i < 8; ++i)
#pragma unroll
        for (int j = 0; j < 8; ++j) acc[i][j] = 0.f;

    for (int kt = 0; kt < D_IN / 32; ++kt) {   // k tiles ascending
        __syncthreads();
#pragma unroll
        for (int i = 0; i < 4; ++i) {
            int e = tid + i * 256;          // 0..1023
            int r = e >> 3, k4 = e & 7;
            float4 v = make_float4(0.f, 0.f, 0.f, 0.f);
            int gr = row0 + r;
            if (gr < M) v = *(const float4*)(A + (size_t)gr * D_IN + kt * 32 + k4 * 4);
            sA[k4 * 4 + 0][r] = v.x; sA[k4 * 4 + 1][r] = v.y;
            sA[k4 * 4 + 2][r] = v.z; sA[k4 * 4 + 3][r] = v.w;
        }
#pragma unroll
        for (int i = 0; i < 4; ++i) {
            int e = tid + i * 256;          // 0..1023
            int k = e >> 5, n4 = e & 31;
            float4 v = *(const float4*)(B + (size_t)(kt * 32 + k) * D_IN + col0 + n4 * 4);
            *(float4*)&sB[k][n4 * 4] = v;
        }
        __syncthreads();
#pragma unroll
        for (int kk = 0; kk < 32; ++kk) {   // k ascending within tile
            float a[8], b[8];
            *(float4*)&a[0] = *(const float4*)&sA[kk][ty * 8];
            *(float4*)&a[4] = *(const float4*)&sA[kk][ty * 8 + 4];
            *(float4*)&b[0] = *(const float4*)&sB[kk][tx * 8];
            *(float4*)&b[4] = *(const float4*)&sB[kk][tx * 8 + 4];
#pragma unroll
            for (int i = 0; i < 8; ++i)
#pragma unroll
                for (int j = 0; j < 8; ++j)
                    acc[i][j] = __fmaf_rn(a[i], b[j], acc[i][j]);
        }
    }
#pragma unroll
    for (int i = 0; i < 8; ++i) {
        int gr = row0 + ty * 8 + i;
        if (gr < M) {
            float* hp = g_h + (size_t)gr * D_IN + col0 + tx * 8;
            *(float4*)hp       = make_float4(acc[i][0], acc[i][1], acc[i][2], acc[i][3]);
            *(float4*)(hp + 4) = make_float4(acc[i][4], acc[i][5], acc[i][6], acc[i][7]);
            uint4 bb;
            bb.x = bf2u(__floats2bfloat162_rn(acc[i][0], acc[i][1]));
            bb.y = bf2u(__floats2bfloat162_rn(acc[i][2], acc[i][3]));
            bb.z = bf2u(__floats2bfloat162_rn(acc[i][4], acc[i][5]));
            bb.w = bf2u(__floats2bfloat162_rn(acc[i][6], acc[i][7]));
            *(uint4*)(g_hb + (size_t)gr * D_IN + col0 + tx * 8) = bb;
        }
    }
}

// ---------------------------------------------------------------------------
// Kernel 2: row sum-of-squares (EXACT chain kept from R4).
// ---------------------------------------------------------------------------
__global__ void k_rowsq(const float* __restrict__ src, float* __restrict__ dst, int M)
{
    int warp = (blockIdx.x * blockDim.x + threadIdx.x) >> 5;
    int lane = threadIdx.x & 31;
    if (warp >= M) return;
    const float* p = src + (size_t)warp * D_IN;
    float s = 0.f;
#pragma unroll
    for (int j = 0; j < D_IN / 32; ++j) {
        float v = p[lane + j * 32];
        s = __fmaf_rn(v, v, s);
    }
#pragma unroll
    for (int off = 16; off; off >>= 1)
        s = __fadd_rn(s, __shfl_down_sync(0xffffffffu, s, off));
    if (lane == 0) dst[warp] = s;
}

// ---------------------------------------------------------------------------
// Kernel 3: codebook -> bf16
// ---------------------------------------------------------------------------
__global__ void k_cbconv(const float* __restrict__ cb)
{
    int r = blockIdx.x;
    for (int k = threadIdx.x; k < D_IN; k += blockDim.x)
        g_cbb[(size_t)r * D_IN + k] = __float2bfloat16_rn(cb[(size_t)r * D_IN + k]);
}

// ---------------------------------------------------------------------------
// Kernel 4: proj = 0.25 * codebook @ head_w (R11-validated 32-codes/CTA form;
// the 8-codes retile quadrupled hw load traffic and regressed).
// ---------------------------------------------------------------------------
__global__ __launch_bounds__(256) void k_proj(
    const float* __restrict__ cb, const float* __restrict__ hw)
{
    __shared__ float scb[32][64];
    const int tid = threadIdx.x;
    const int c0 = blockIdx.x * 32;

    float acc[32];
#pragma unroll
    for (int r = 0; r < 32; ++r) acc[r] = 0.f;

    for (int kt = 0; kt < D_IN / 64; ++kt) {
        __syncthreads();
#pragma unroll
        for (int i = 0; i < 2; ++i) {
            int e = tid + i * 256;
            int r = e >> 4, k4 = e & 15;
            *(float4*)&scb[r][k4 * 4] =
                *(const float4*)(cb + (size_t)(c0 + r) * D_IN + kt * 64 + k4 * 4);
        }
        __syncthreads();
#pragma unroll 8
        for (int kk = 0; kk < 64; ++kk) {
            float w = hw[(size_t)(kt * 64 + kk) * D_OUT + tid];
#pragma unroll
            for (int r = 0; r < 32; ++r) acc[r] = __fmaf_rn(scb[r][kk], w, acc[r]);
        }
    }
#pragma unroll
    for (int r = 0; r < 32; ++r)
        g_proj[(size_t)(c0 + r) * D_OUT + tid] = 0.25f * acc[r];
}

// ---------------------------------------------------------------------------
// Kernel 5: approximate distance pass on tensor cores (bf16 HMMA, base ISA).
// R11/R5-validated form: sequential load -> sync -> mma per 128-k slab.
// Block: 128 rows x 2048 codes (16 chunks of 128), 256 threads / 8 warps.
// ---------------------------------------------------------------------------
__global__ __launch_bounds__(256) void k_approx(int M)
{
    extern __shared__ char sm[];
    const unsigned sbase = (unsigned)__cvta_generic_to_shared(sm);
    const unsigned sBbase = sbase + 131072;
    float (*ssc)[132] = (float (*)[132])(sm + 163840);

    const int tid = threadIdx.x;
    const int lane = tid & 31;
    const int warp = tid >> 5;
    const int wm = warp & 3, wn = warp >> 2;
    const int row0 = blockIdx.x * 128;

#pragma unroll
    for (int it = 0; it < 32; ++it) {
        int idx = tid + it * 256;
        int m = idx >> 6, u = idx & 63;
        uint4 v = ((const uint4*)g_hb)[(size_t)(row0 + m) * 64 + u];
        *(uint4*)(sm + m * 1024 + ((u ^ (m & 7)) << 4)) = v;
    }

    float tv[8]; int tix[8];
#pragma unroll
    for (int q = 0; q < 8; ++q) { tv[q] = 3.4e38f; tix[q] = 0; }

    for (int ch = 0; ch < 16; ++ch) {
        const int c0 = ch * 128;
        float d[2][8][4];
#pragma unroll
        for (int i = 0; i < 2; ++i)
#pragma unroll
            for (int j = 0; j < 8; ++j)
#pragma unroll
                for (int q = 0; q < 4; ++q) d[i][j][q] = 0.f;

        for (int kb = 0; kb < 512; kb += 128) {
            __syncthreads();
#pragma unroll
            for (int it = 0; it < 8; ++it) {
                int idx = tid + it * 256;
                int n = idx >> 4, u16 = idx & 15;
                uint4 v = ((const uint4*)g_cbb)[(size_t)(c0 + n) * 64 + (kb >> 3) + u16];
                *(uint4*)(sm + 131072 + n * 256 + ((u16 ^ (n & 7)) << 4)) = v;
            }
            __syncthreads();
#pragma unroll
            for (int s = 0; s < 8; ++s) {
                unsigned a[2][4], b[8][2];
                const int uA = (kb >> 3) + s * 2;
#pragma unroll
                for (int i = 0; i < 2; ++i) {
                    int rrow = wm * 32 + i * 16 + ((lane >> 3) & 1) * 8 + (lane & 7);
                    int un = uA + (lane >> 4);
                    unsigned ad = sbase + rrow * 1024 + ((un ^ (rrow & 7)) << 4);
                    LDSM4(a[i][0], a[i][1], a[i][2], a[i][3], ad);
                }
#pragma unroll
                for (int jp = 0; jp < 4; ++jp) {
                    int nr = wn * 64 + jp * 16 + (lane >> 4) * 8 + (lane & 7);
                    int un = s * 2 + ((lane >> 3) & 1);
                    unsigned ad = sBbase + nr * 256 + ((un ^ (nr & 7)) << 4);
                    LDSM4(b[2 * jp][0], b[2 * jp][1], b[2 * jp + 1][0], b[2 * jp + 1][1], ad);
                }
#pragma unroll
                for (int i = 0; i < 2; ++i)
#pragma unroll
                    for (int j = 0; j < 8; ++j)
                        MMA16816(d[i][j], a[i], b[j]);
            }
        }
        __syncthreads();
        {
            const int g = lane >> 2, t4 = lane & 3;
#pragma unroll
            for (int i = 0; i < 2; ++i) {
                int rb = wm * 32 + i * 16 + g;
#pragma unroll
                for (int j = 0; j < 8; ++j) {
                    int cw = wn * 64 + j * 8 + t4 * 2;
                    ssc[rb][cw]         = d[i][j][0];
                    ssc[rb][cw + 1]     = d[i][j][1];
                    ssc[rb + 8][cw]     = d[i][j][2];
                    ssc[rb + 8][cw + 1] = d[i][j][3];
                }
            }
        }
        __syncthreads();
        {
            const int srw = tid >> 1, shalf = tid & 1;
#pragma unroll 4
            for (int cc = 0; cc < 64; ++cc) {
                int c = shalf * 64 + cc;
                float s = __fmaf_rn(-2.f, ssc[srw][c], g_cbsq[c0 + c]);
                if (s < tv[7]) {
                    float v = s; int ii = c0 + c;
#pragma unroll
                    for (int q = 0; q < 8; ++q) {
                        if (v < tv[q]) {
                            float tvv = tv[q]; int tii = tix[q];
                            tv[q] = v; tix[q] = ii; v = tvv; ii = tii;
                        }
                    }
                }
            }
        }
    }

    const int srw = tid >> 1, shalf = tid & 1;
#pragma unroll
    for (int q = 0; q < 8; ++q)
        g_cand[(size_t)(row0 + srw) * 16 + shalf * 8 + q] = tix[q];
}

// ---------------------------------------------------------------------------
// Kernel 6: exact rescore, 2 rows per warp (lanes 0-15 row A, 16-31 row B).
// Halves total warp count at unchanged per-warp work. Per-candidate chain
// identical: sequential ascending-k __fmaf_rn dot; dist = fl(fl(hsq-2dot)+cbsq);
// rank by (dist_bits << 32 | index), min-reduce within each 16-lane half.
// ---------------------------------------------------------------------------
__global__ __launch_bounds__(256) void k_exact(
    const float* __restrict__ cb, const float* __restrict__ bias,
    float* __restrict__ out, int M)
{
    __shared__ float sh[16][D_IN];
    const int warp = threadIdx.x >> 5, lane = threadIdx.x & 31;
    const int hl = lane >> 4, ln = lane & 15;
    const int row = blockIdx.x * 16 + warp * 2 + hl;
    const bool valid = row < M;

    if (valid) {
        float4* s4 = (float4*)sh[warp * 2 + hl];
        const float4* hrow = (const float4*)(g_h + (size_t)row * D_IN);
#pragma unroll
        for (int i = ln; i < D_IN / 4; i += 16) s4[i] = hrow[i];
    }
    __syncwarp();

    u64 key = 0xFFFFFFFFFFFFFFFFull;
    if (valid) {
        int c = g_cand[(size_t)row * 16 + ln];
        const float4* sh4 = (const float4*)sh[warp * 2 + hl];
        const float4* crow = (const float4*)(cb + (size_t)c * D_IN);
        float acc = 0.f;
#pragma unroll 8
        for (int i = 0; i < D_IN / 4; ++i) {
            float4 hv = sh4[i];
            float4 cv = crow[i];
            acc = __fmaf_rn(hv.x, cv.x, acc);
            acc = __fmaf_rn(hv.y, cv.y, acc);
            acc = __fmaf_rn(hv.z, cv.z, acc);
            acc = __fmaf_rn(hv.w, cv.w, acc);
        }
        float t = __fmaf_rn(-2.0f, acc, g_hsq[row]);
        float dd = __fadd_rn(t, g_cbsq[c]);
        key = ((u64)__float_as_uint(dd) << 32) | (unsigned)c;
    }
    __syncwarp();

    int cq[4];
#pragma unroll
    for (int q = 0; q < 4; ++q) {
        u64 m = key;
#pragma unroll
        for (int off = 8; off; off >>= 1) {   // xor within 16-lane half
            u64 o = __shfl_xor_sync(0xffffffffu, m, off);
            if (o < m) m = o;
        }
        cq[q] = (int)(m & 0xFFFFFFFFu);
        if (key == m) key = 0xFFFFFFFFFFFFFFFFull;
    }

    if (valid) {
#pragma unroll
        for (int j = 0; j < D_OUT / 16; ++j) {
            int col = ln + j * 16;
            float v = bias[col];
#pragma unroll
            for (int q = 0; q < 4; ++q)
                v += g_proj[(size_t)cq[q] * D_OUT + col];
            out[(size_t)row * D_OUT + col] = v;
        }
    }
}

// ---------------------------------------------------------------------------
// Launch
// ---------------------------------------------------------------------------
extern "C" void kernel_launch(void* const* d_in, const int* in_sizes, int n_in,
                              void* d_out, int out_size)
{
    const float* x  = (const float*)d_in[0];   // [M, 512]
    const float* W  = (const float*)d_in[1];   // [512, 512]
    const float* cb = (const float*)d_in[2];   // [2048, 512]
    const float* hw = (const float*)d_in[3];   // [512, 256]
    const float* hb = (const float*)d_in[4];   // [256]
    float* out = (float*)d_out;                // [M, 256]

    const int M = in_sizes[0] / D_IN;
    const int mb2 = (M + 127) / 128;

    float* d_hsq;  cudaGetSymbolAddress((void**)&d_hsq,  g_hsq);
    float* d_cbsq; cudaGetSymbolAddress((void**)&d_cbsq, g_cbsq);
    float* d_hbuf; cudaGetSymbolAddress((void**)&d_hbuf, g_h);

    const int approx_smem = 131072 + 32768 + 128 * 132 * 4;  // 231424 B
    cudaFuncSetAttribute(k_approx, cudaFuncAttributeMaxDynamicSharedMemorySize,
                         approx_smem);

    k_gemm_xw<<<dim3(mb2, 4), 256>>>(x, W, M);
    k_rowsq<<<(M * 32 + 255) / 256, 256>>>(d_hbuf, d_hsq, M);
    k_rowsq<<<(NUM_CODES * 32) / 256, 256>>>(cb, d_cbsq, NUM_CODES);
    k_cbconv<<<NUM_CODES, 256>>>(cb);
    k_proj<<<NUM_CODES / 32, 256>>>(cb, hw);
    k_approx<<<mb2, 256, approx_smem>>>(M);
    k_exact<<<(M + 15) / 16, 256>>>(cb, hb, out, M);
}

// round 15
// speedup vs baseline: 1.1105x; 1.1105x over previous
#include <cuda_runtime.h>
#include <cuda_bf16.h>
#include <cstdint>
#include <cstring>

#define D_IN      512
#define NUM_CODES 2048
#define D_OUT     256
#define MAX_ROWS  100096   // ceil(100000/128)*128

typedef unsigned long long u64;

// Scratch (no allocations allowed -> __device__ globals, zero-initialized)
__device__ float g_h[(size_t)MAX_ROWS * D_IN];            // projected features (exact fp32)
__device__ __nv_bfloat16 g_hb[(size_t)MAX_ROWS * D_IN];   // bf16 copy of h
__device__ __nv_bfloat16 g_cbb[(size_t)NUM_CODES * D_IN]; // bf16 codebook
__device__ float g_hsq[MAX_ROWS];                         // fl32(||h||^2)
__device__ float g_proj[(size_t)NUM_CODES * D_OUT];       // 0.25 * codebook @ head_w
__device__ float g_cbsq[NUM_CODES];                       // fl32(||codebook_c||^2)
__device__ int   g_cand[(size_t)MAX_ROWS * 16];           // 16 candidates per row

#define LDSM4(r0,r1,r2,r3,addr) \
    asm volatile("ldmatrix.sync.aligned.m8n8.x4.shared.b16 {%0,%1,%2,%3},[%4];" \
        : "=r"(r0), "=r"(r1), "=r"(r2), "=r"(r3) : "r"(addr))

#define MMA16816(d, a, b) \
    asm volatile("mma.sync.aligned.m16n8k16.row.col.f32.bf16.bf16.f32 " \
        "{%0,%1,%2,%3},{%4,%5,%6,%7},{%8,%9},{%0,%1,%2,%3};" \
        : "+f"((d)[0]), "+f"((d)[1]), "+f"((d)[2]), "+f"((d)[3]) \
        : "r"((a)[0]), "r"((a)[1]), "r"((a)[2]), "r"((a)[3]), "r"((b)[0]), "r"((b)[1]))

__device__ __forceinline__ unsigned bf2u(__nv_bfloat162 v) {
    unsigned u; memcpy(&u, &v, 4); return u;
}

// ---------------------------------------------------------------------------
// Kernel 1: h = x @ linear_proj   (M x 512) @ (512 x 512)
// EXACT bits: single fp32 accumulator per element, __fmaf_rn, k strictly
// ascending. Tile 128x128, BK=32, 256 threads, 8x8/thread (R11-validated).
// Epilogue also emits bf16 h for the approximate pass.
// ---------------------------------------------------------------------------
__global__ __launch_bounds__(256, 2) void k_gemm_xw(
    const float* __restrict__ A, const float* __restrict__ B, int M)
{
    __shared__ float sA[32][132];   // [k][m]
    __shared__ float sB[32][132];   // [k][n]

    const int tid = threadIdx.x;
    const int tx = tid & 15, ty = tid >> 4;
    const int row0 = blockIdx.x * 128;
    const int col0 = blockIdx.y * 128;

    float acc[8][8];
#pragma unroll
    for (int i = 0; i < 8; ++i)
#pragma unroll
        for (int j = 0; j < 8; ++j) acc[i][j] = 0.f;

    for (int kt = 0; kt < D_IN / 32; ++kt) {   // k tiles ascending
        __syncthreads();
#pragma unroll
        for (int i = 0; i < 4; ++i) {
            int e = tid + i * 256;          // 0..1023
            int r = e >> 3, k4 = e & 7;
            float4 v = make_float4(0.f, 0.f, 0.f, 0.f);
            int gr = row0 + r;
            if (gr < M) v = *(const float4*)(A + (size_t)gr * D_IN + kt * 32 + k4 * 4);
            sA[k4 * 4 + 0][r] = v.x; sA[k4 * 4 + 1][r] = v.y;
            sA[k4 * 4 + 2][r] = v.z; sA[k4 * 4 + 3][r] = v.w;
        }
#pragma unroll
        for (int i = 0; i < 4; ++i) {
            int e = tid + i * 256;          // 0..1023
            int k = e >> 5, n4 = e & 31;
            float4 v = *(const float4*)(B + (size_t)(kt * 32 + k) * D_IN + col0 + n4 * 4);
            *(float4*)&sB[k][n4 * 4] = v;
        }
        __syncthreads();
#pragma unroll
        for (int kk = 0; kk < 32; ++kk) {   // k ascending within tile
            float a[8], b[8];
            *(float4*)&a[0] = *(const float4*)&sA[kk][ty * 8];
            *(float4*)&a[4] = *(const float4*)&sA[kk][ty * 8 + 4];
            *(float4*)&b[0] = *(const float4*)&sB[kk][tx * 8];
            *(float4*)&b[4] = *(const float4*)&sB[kk][tx * 8 + 4];
#pragma unroll
            for (int i = 0; i < 8; ++i)
#pragma unroll
                for (int j = 0; j < 8; ++j)
                    acc[i][j] = __fmaf_rn(a[i], b[j], acc[i][j]);
        }
    }
#pragma unroll
    for (int i = 0; i < 8; ++i) {
        int gr = row0 + ty * 8 + i;
        if (gr < M) {
            float* hp = g_h + (size_t)gr * D_IN + col0 + tx * 8;
            *(float4*)hp       = make_float4(acc[i][0], acc[i][1], acc[i][2], acc[i][3]);
            *(float4*)(hp + 4) = make_float4(acc[i][4], acc[i][5], acc[i][6], acc[i][7]);
            uint4 bb;
            bb.x = bf2u(__floats2bfloat162_rn(acc[i][0], acc[i][1]));
            bb.y = bf2u(__floats2bfloat162_rn(acc[i][2], acc[i][3]));
            bb.z = bf2u(__floats2bfloat162_rn(acc[i][4], acc[i][5]));
            bb.w = bf2u(__floats2bfloat162_rn(acc[i][6], acc[i][7]));
            *(uint4*)(g_hb + (size_t)gr * D_IN + col0 + tx * 8) = bb;
        }
    }
}

// ---------------------------------------------------------------------------
// Kernel 2: row sum-of-squares (EXACT chain kept from R4).
// ---------------------------------------------------------------------------
__global__ void k_rowsq(const float* __restrict__ src, float* __restrict__ dst, int M)
{
    int warp = (blockIdx.x * blockDim.x + threadIdx.x) >> 5;
    int lane = threadIdx.x & 31;
    if (warp >= M) return;
    const float* p = src + (size_t)warp * D_IN;
    float s = 0.f;
#pragma unroll
    for (int j = 0; j < D_IN / 32; ++j) {
        float v = p[lane + j * 32];
        s = __fmaf_rn(v, v, s);
    }
#pragma unroll
    for (int off = 16; off; off >>= 1)
        s = __fadd_rn(s, __shfl_down_sync(0xffffffffu, s, off));
    if (lane == 0) dst[warp] = s;
}

// ---------------------------------------------------------------------------
// Kernel 3: codebook -> bf16
// ---------------------------------------------------------------------------
__global__ void k_cbconv(const float* __restrict__ cb)
{
    int r = blockIdx.x;
    for (int k = threadIdx.x; k < D_IN; k += blockDim.x)
        g_cbb[(size_t)r * D_IN + k] = __float2bfloat16_rn(cb[(size_t)r * D_IN + k]);
}

// ---------------------------------------------------------------------------
// Kernel 4: proj = 0.25 * codebook @ head_w (R11-validated 32-codes/CTA form).
// ---------------------------------------------------------------------------
__global__ __launch_bounds__(256) void k_proj(
    const float* __restrict__ cb, const float* __restrict__ hw)
{
    __shared__ float scb[32][64];
    const int tid = threadIdx.x;
    const int c0 = blockIdx.x * 32;

    float acc[32];
#pragma unroll
    for (int r = 0; r < 32; ++r) acc[r] = 0.f;

    for (int kt = 0; kt < D_IN / 64; ++kt) {
        __syncthreads();
#pragma unroll
        for (int i = 0; i < 2; ++i) {
            int e = tid + i * 256;
            int r = e >> 4, k4 = e & 15;
            *(float4*)&scb[r][k4 * 4] =
                *(const float4*)(cb + (size_t)(c0 + r) * D_IN + kt * 64 + k4 * 4);
        }
        __syncthreads();
#pragma unroll 8
        for (int kk = 0; kk < 64; ++kk) {
            float w = hw[(size_t)(kt * 64 + kk) * D_OUT + tid];
#pragma unroll
            for (int r = 0; r < 32; ++r) acc[r] = __fmaf_rn(scb[r][kk], w, acc[r]);
        }
    }
#pragma unroll
    for (int r = 0; r < 32; ++r)
        g_proj[(size_t)(c0 + r) * D_OUT + tid] = 0.25f * acc[r];
}

// ---------------------------------------------------------------------------
// Kernel 5: approximate distance pass (bf16 HMMA) with software-pipelined B
// (R12-validated: -87us, correctness-safe). Two 32KB slab buffers; buffer1
// overlaid on the score region (written only after last MMA of the chunk).
// ---------------------------------------------------------------------------
__global__ __launch_bounds__(256) void k_approx(int M)
{
    extern __shared__ char sm[];
    const unsigned sbase = (unsigned)__cvta_generic_to_shared(sm);
    const unsigned bB0 = sbase + 131072;          // B buffer 0
    const unsigned bB1 = sbase + 163840;          // B buffer 1 (== ssc start)
    float (*ssc)[132] = (float (*)[132])(sm + 163840);

    const int tid = threadIdx.x;
    const int lane = tid & 31;
    const int warp = tid >> 5;
    const int wm = warp & 3, wn = warp >> 2;
    const int row0 = blockIdx.x * 128;

    // A: 128 rows x 512 bf16 = 1024B rows, 64x16B units, swizzled u^(m&7)
#pragma unroll
    for (int it = 0; it < 32; ++it) {
        int idx = tid + it * 256;
        int m = idx >> 6, u = idx & 63;
        uint4 v = ((const uint4*)g_hb)[(size_t)(row0 + m) * 64 + u];
        *(uint4*)(sm + m * 1024 + ((u ^ (m & 7)) << 4)) = v;
    }

    float tv[8]; int tix[8];
#pragma unroll
    for (int q = 0; q < 8; ++q) { tv[q] = 3.4e38f; tix[q] = 0; }

    for (int ch = 0; ch < 16; ++ch) {
        const int c0 = ch * 128;
        float d[2][8][4];
#pragma unroll
        for (int i = 0; i < 2; ++i)
#pragma unroll
            for (int j = 0; j < 8; ++j)
#pragma unroll
                for (int q = 0; q < 4; ++q) d[i][j][q] = 0.f;

        auto load_slab = [&](int kbi, unsigned dstoff) {
#pragma unroll
            for (int it = 0; it < 8; ++it) {
                int idx = tid + it * 256;
                int n = idx >> 4, u16 = idx & 15;
                uint4 v = ((const uint4*)g_cbb)[(size_t)(c0 + n) * 64 + kbi * 16 + u16];
                *(uint4*)(sm + dstoff + n * 256 + ((u16 ^ (n & 7)) << 4)) = v;
            }
        };
        auto do_mma = [&](int kbi, unsigned bB) {
#pragma unroll
            for (int s = 0; s < 8; ++s) {
                unsigned a[2][4], b[8][2];
                const int uA = kbi * 16 + s * 2;
#pragma unroll
                for (int i = 0; i < 2; ++i) {
                    int rrow = wm * 32 + i * 16 + ((lane >> 3) & 1) * 8 + (lane & 7);
                    int un = uA + (lane >> 4);
                    unsigned ad = sbase + rrow * 1024 + ((un ^ (rrow & 7)) << 4);
                    LDSM4(a[i][0], a[i][1], a[i][2], a[i][3], ad);
                }
#pragma unroll
                for (int jp = 0; jp < 4; ++jp) {
                    int nr = wn * 64 + jp * 16 + (lane >> 4) * 8 + (lane & 7);
                    int un = s * 2 + ((lane >> 3) & 1);
                    unsigned ad = bB + nr * 256 + ((un ^ (nr & 7)) << 4);
                    LDSM4(b[2 * jp][0], b[2 * jp][1], b[2 * jp + 1][0], b[2 * jp + 1][1], ad);
                }
#pragma unroll
                for (int i = 0; i < 2; ++i)
#pragma unroll
                    for (int j = 0; j < 8; ++j)
                        MMA16816(d[i][j], a[i], b[j]);
            }
        };

        __syncthreads();                 // prev scan done: ssc/B1 and B0 free
        load_slab(0, 131072);
        __syncthreads();                 // B0 ready
        load_slab(1, 163840);            // B1 loads overlap mma(slab0)
        do_mma(0, bB0);
        __syncthreads();                 // B1 ready; B0 free
        load_slab(2, 131072);            // B0 loads overlap mma(slab1)
        do_mma(1, bB1);
        __syncthreads();                 // B0 ready; B1 free
        load_slab(3, 163840);            // B1 loads overlap mma(slab2)
        do_mma(2, bB0);
        __syncthreads();                 // B1 ready
        do_mma(3, bB1);
        __syncthreads();                 // all threads done reading B1

        {
            const int g = lane >> 2, t4 = lane & 3;
#pragma unroll
            for (int i = 0; i < 2; ++i) {
                int rb = wm * 32 + i * 16 + g;
#pragma unroll
                for (int j = 0; j < 8; ++j) {
                    int cw = wn * 64 + j * 8 + t4 * 2;
                    ssc[rb][cw]         = d[i][j][0];
                    ssc[rb][cw + 1]     = d[i][j][1];
                    ssc[rb + 8][cw]     = d[i][j][2];
                    ssc[rb + 8][cw + 1] = d[i][j][3];
                }
            }
        }
        __syncthreads();
        {
            const int srw = tid >> 1, shalf = tid & 1;
#pragma unroll 4
            for (int cc = 0; cc < 64; ++cc) {
                int c = shalf * 64 + cc;
                float s = __fmaf_rn(-2.f, ssc[srw][c], g_cbsq[c0 + c]);
                if (s < tv[7]) {
                    float v = s; int ii = c0 + c;
#pragma unroll
                    for (int q = 0; q < 8; ++q) {
                        if (v < tv[q]) {
                            float tvv = tv[q]; int tii = tix[q];
                            tv[q] = v; tix[q] = ii; v = tvv; ii = tii;
                        }
                    }
                }
            }
        }
    }

    const int srw = tid >> 1, shalf = tid & 1;
#pragma unroll
    for (int q = 0; q < 8; ++q)
        g_cand[(size_t)(row0 + srw) * 16 + shalf * 8 + q] = tix[q];
}

// ---------------------------------------------------------------------------
// Kernel 6: exact rescore (R11-validated form: one warp per row, 16 active
// lanes -> maximal warp-level MLP for the latency-bound cb gathers).
// EXACT chain: sequential ascending-k __fmaf_rn dot; dist = fl(fl(hsq-2dot)+cbsq);
// rank by (dist_bits << 32 | index).
// ---------------------------------------------------------------------------
__global__ __launch_bounds__(256) void k_exact(
    const float* __restrict__ cb, const float* __restrict__ bias,
    float* __restrict__ out, int M)
{
    __shared__ float sh[8][D_IN];
    const int warp = threadIdx.x >> 5, lane = threadIdx.x & 31;
    const int row = blockIdx.x * 8 + warp;
    if (row >= M) return;

    float4* sh4 = (float4*)sh[warp];
    const float4* hrow = (const float4*)(g_h + (size_t)row * D_IN);
#pragma unroll
    for (int i = lane; i < D_IN / 4; i += 32) sh4[i] = hrow[i];
    __syncwarp();

    u64 key = 0xFFFFFFFFFFFFFFFFull;
    if (lane < 16) {
        int c = g_cand[(size_t)row * 16 + lane];
        const float4* crow = (const float4*)(cb + (size_t)c * D_IN);
        float acc = 0.f;
#pragma unroll 8
        for (int i = 0; i < D_IN / 4; ++i) {
            float4 hv = sh4[i];
            float4 cv = crow[i];
            acc = __fmaf_rn(hv.x, cv.x, acc);
            acc = __fmaf_rn(hv.y, cv.y, acc);
            acc = __fmaf_rn(hv.z, cv.z, acc);
            acc = __fmaf_rn(hv.w, cv.w, acc);
        }
        float t = __fmaf_rn(-2.0f, acc, g_hsq[row]);
        float dd = __fadd_rn(t, g_cbsq[c]);
        key = ((u64)__float_as_uint(dd) << 32) | (unsigned)c;
    }
    __syncwarp();

    int cq[4];
#pragma unroll
    for (int q = 0; q < 4; ++q) {
        u64 m = key;
#pragma unroll
        for (int off = 16; off; off >>= 1) {
            u64 o = __shfl_xor_sync(0xffffffffu, m, off);
            if (o < m) m = o;
        }
        cq[q] = (int)(m & 0xFFFFFFFFu);
        if (key == m) key = 0xFFFFFFFFFFFFFFFFull;
    }

#pragma unroll
    for (int j = 0; j < D_OUT / 32; ++j) {
        int col = lane + j * 32;
        float v = bias[col];
#pragma unroll
        for (int q = 0; q < 4; ++q)
            v += g_proj[(size_t)cq[q] * D_OUT + col];
        out[(size_t)row * D_OUT + col] = v;
    }
}

// ---------------------------------------------------------------------------
// Launch
// ---------------------------------------------------------------------------
extern "C" void kernel_launch(void* const* d_in, const int* in_sizes, int n_in,
                              void* d_out, int out_size)
{
    const float* x  = (const float*)d_in[0];   // [M, 512]
    const float* W  = (const float*)d_in[1];   // [512, 512]
    const float* cb = (const float*)d_in[2];   // [2048, 512]
    const float* hw = (const float*)d_in[3];   // [512, 256]
    const float* hb = (const float*)d_in[4];   // [256]
    float* out = (float*)d_out;                // [M, 256]

    const int M = in_sizes[0] / D_IN;
    const int mb2 = (M + 127) / 128;

    float* d_hsq;  cudaGetSymbolAddress((void**)&d_hsq,  g_hsq);
    float* d_cbsq; cudaGetSymbolAddress((void**)&d_cbsq, g_cbsq);
    float* d_hbuf; cudaGetSymbolAddress((void**)&d_hbuf, g_h);

    const int approx_smem = 131072 + 32768 + 128 * 132 * 4;  // 231424 B
    cudaFuncSetAttribute(k_approx, cudaFuncAttributeMaxDynamicSharedMemorySize,
                         approx_smem);

    k_gemm_xw<<<dim3(mb2, 4), 256>>>(x, W, M);
    k_rowsq<<<(M * 32 + 255) / 256, 256>>>(d_hbuf, d_hsq, M);
    k_rowsq<<<(NUM_CODES * 32) / 256, 256>>>(cb, d_cbsq, NUM_CODES);
    k_cbconv<<<NUM_CODES, 256>>>(cb);
    k_proj<<<NUM_CODES / 32, 256>>>(cb, hw);
    k_approx<<<mb2, 256, approx_smem>>>(M);
    k_exact<<<(M + 7) / 8, 256>>>(cb, hb, out, M);
}

// round 16
// speedup vs baseline: 1.1273x; 1.0151x over previous
#include <cuda_runtime.h>
#include <cuda_bf16.h>
#include <cstdint>
#include <cstring>

#define D_IN      512
#define NUM_CODES 2048
#define D_OUT     256
#define MAX_ROWS  100096   // ceil(100000/128)*128

typedef unsigned long long u64;

// Scratch (no allocations allowed -> __device__ globals, zero-initialized)
__device__ float g_h[(size_t)MAX_ROWS * D_IN];            // projected features (exact fp32)
__device__ __nv_bfloat16 g_hb[(size_t)MAX_ROWS * D_IN];   // bf16 copy of h
__device__ __nv_bfloat16 g_cbb[(size_t)NUM_CODES * D_IN]; // bf16 codebook
__device__ float g_proj[(size_t)NUM_CODES * D_OUT];       // 0.25 * codebook @ head_w
__device__ float g_cbsq[NUM_CODES];                       // fl32(||codebook_c||^2)
__device__ int   g_cand[(size_t)MAX_ROWS * 16];           // 16 candidates per row

#define LDSM4(r0,r1,r2,r3,addr) \
    asm volatile("ldmatrix.sync.aligned.m8n8.x4.shared.b16 {%0,%1,%2,%3},[%4];" \
        : "=r"(r0), "=r"(r1), "=r"(r2), "=r"(r3) : "r"(addr))

#define MMA16816(d, a, b) \
    asm volatile("mma.sync.aligned.m16n8k16.row.col.f32.bf16.bf16.f32 " \
        "{%0,%1,%2,%3},{%4,%5,%6,%7},{%8,%9},{%0,%1,%2,%3};" \
        : "+f"((d)[0]), "+f"((d)[1]), "+f"((d)[2]), "+f"((d)[3]) \
        : "r"((a)[0]), "r"((a)[1]), "r"((a)[2]), "r"((a)[3]), "r"((b)[0]), "r"((b)[1]))

__device__ __forceinline__ unsigned bf2u(__nv_bfloat162 v) {
    unsigned u; memcpy(&u, &v, 4); return u;
}

// ---------------------------------------------------------------------------
// Kernel 1: h = x @ linear_proj   (M x 512) @ (512 x 512)
// EXACT bits: single fp32 accumulator per element, __fmaf_rn, k strictly
// ascending. Tile 128x128, BK=32, 256 threads, 8x8/thread (R11-validated).
// Epilogue also emits bf16 h for the approximate pass.
// ---------------------------------------------------------------------------
__global__ __launch_bounds__(256, 2) void k_gemm_xw(
    const float* __restrict__ A, const float* __restrict__ B, int M)
{
    __shared__ float sA[32][132];   // [k][m]
    __shared__ float sB[32][132];   // [k][n]

    const int tid = threadIdx.x;
    const int tx = tid & 15, ty = tid >> 4;
    const int row0 = blockIdx.x * 128;
    const int col0 = blockIdx.y * 128;

    float acc[8][8];
#pragma unroll
    for (int i = 0; i < 8; ++i)
#pragma unroll
        for (int j = 0; j < 8; ++j) acc[i][j] = 0.f;

    for (int kt = 0; kt < D_IN / 32; ++kt) {   // k tiles ascending
        __syncthreads();
#pragma unroll
        for (int i = 0; i < 4; ++i) {
            int e = tid + i * 256;          // 0..1023
            int r = e >> 3, k4 = e & 7;
            float4 v = make_float4(0.f, 0.f, 0.f, 0.f);
            int gr = row0 + r;
            if (gr < M) v = *(const float4*)(A + (size_t)gr * D_IN + kt * 32 + k4 * 4);
            sA[k4 * 4 + 0][r] = v.x; sA[k4 * 4 + 1][r] = v.y;
            sA[k4 * 4 + 2][r] = v.z; sA[k4 * 4 + 3][r] = v.w;
        }
#pragma unroll
        for (int i = 0; i < 4; ++i) {
            int e = tid + i * 256;          // 0..1023
            int k = e >> 5, n4 = e & 31;
            float4 v = *(const float4*)(B + (size_t)(kt * 32 + k) * D_IN + col0 + n4 * 4);
            *(float4*)&sB[k][n4 * 4] = v;
        }
        __syncthreads();
#pragma unroll
        for (int kk = 0; kk < 32; ++kk) {   // k ascending within tile
            float a[8], b[8];
            *(float4*)&a[0] = *(const float4*)&sA[kk][ty * 8];
            *(float4*)&a[4] = *(const float4*)&sA[kk][ty * 8 + 4];
            *(float4*)&b[0] = *(const float4*)&sB[kk][tx * 8];
            *(float4*)&b[4] = *(const float4*)&sB[kk][tx * 8 + 4];
#pragma unroll
            for (int i = 0; i < 8; ++i)
#pragma unroll
                for (int j = 0; j < 8; ++j)
                    acc[i][j] = __fmaf_rn(a[i], b[j], acc[i][j]);
        }
    }
#pragma unroll
    for (int i = 0; i < 8; ++i) {
        int gr = row0 + ty * 8 + i;
        if (gr < M) {
            float* hp = g_h + (size_t)gr * D_IN + col0 + tx * 8;
            *(float4*)hp       = make_float4(acc[i][0], acc[i][1], acc[i][2], acc[i][3]);
            *(float4*)(hp + 4) = make_float4(acc[i][4], acc[i][5], acc[i][6], acc[i][7]);
            uint4 bb;
            bb.x = bf2u(__floats2bfloat162_rn(acc[i][0], acc[i][1]));
            bb.y = bf2u(__floats2bfloat162_rn(acc[i][2], acc[i][3]));
            bb.z = bf2u(__floats2bfloat162_rn(acc[i][4], acc[i][5]));
            bb.w = bf2u(__floats2bfloat162_rn(acc[i][6], acc[i][7]));
            *(uint4*)(g_hb + (size_t)gr * D_IN + col0 + tx * 8) = bb;
        }
    }
}

// ---------------------------------------------------------------------------
// Kernel 2: codebook prep — bf16 conversion + cbsq in one pass.
// cbsq chain is EXACTLY the old k_rowsq chain: lane-strided ascending-j
// __fmaf_rn accumulation + shfl_down tree (16,8,4,2,1) + lane-0 store.
// ---------------------------------------------------------------------------
__global__ void k_cbprep(const float* __restrict__ cb)
{
    const int r = blockIdx.x;
    const int tid = threadIdx.x;
    // convert: 2 elems per thread
    {
        int k = tid * 2;
        float v0 = cb[(size_t)r * D_IN + k];
        float v1 = cb[(size_t)r * D_IN + k + 1];
        __nv_bfloat162 p = __floats2bfloat162_rn(v0, v1);
        *(__nv_bfloat162*)(g_cbb + (size_t)r * D_IN + k) = p;
    }
    // cbsq: warp 0 only (L1-hot re-reads), exact k_rowsq chain
    if (tid < 32) {
        const float* p = cb + (size_t)r * D_IN;
        float s = 0.f;
#pragma unroll
        for (int j = 0; j < D_IN / 32; ++j) {
            float v = p[tid + j * 32];
            s = __fmaf_rn(v, v, s);
        }
#pragma unroll
        for (int off = 16; off; off >>= 1)
            s = __fadd_rn(s, __shfl_down_sync(0xffffffffu, s, off));
        if (tid == 0) g_cbsq[r] = s;
    }
}

// ---------------------------------------------------------------------------
// Kernel 3: proj = 0.25 * codebook @ head_w (R11-validated 32-codes/CTA form).
// ---------------------------------------------------------------------------
__global__ __launch_bounds__(256) void k_proj(
    const float* __restrict__ cb, const float* __restrict__ hw)
{
    __shared__ float scb[32][64];
    const int tid = threadIdx.x;
    const int c0 = blockIdx.x * 32;

    float acc[32];
#pragma unroll
    for (int r = 0; r < 32; ++r) acc[r] = 0.f;

    for (int kt = 0; kt < D_IN / 64; ++kt) {
        __syncthreads();
#pragma unroll
        for (int i = 0; i < 2; ++i) {
            int e = tid + i * 256;
            int r = e >> 4, k4 = e & 15;
            *(float4*)&scb[r][k4 * 4] =
                *(const float4*)(cb + (size_t)(c0 + r) * D_IN + kt * 64 + k4 * 4);
        }
        __syncthreads();
#pragma unroll 8
        for (int kk = 0; kk < 64; ++kk) {
            float w = hw[(size_t)(kt * 64 + kk) * D_OUT + tid];
#pragma unroll
            for (int r = 0; r < 32; ++r) acc[r] = __fmaf_rn(scb[r][kk], w, acc[r]);
        }
    }
#pragma unroll
    for (int r = 0; r < 32; ++r)
        g_proj[(size_t)(c0 + r) * D_OUT + tid] = 0.25f * acc[r];
}

// ---------------------------------------------------------------------------
// Kernel 4: approximate distance pass (bf16 HMMA) with software-pipelined B
// (R15-validated). Two 32KB slab buffers; buffer1 overlaid on the score
// region (written only after last MMA of the chunk).
// ---------------------------------------------------------------------------
__global__ __launch_bounds__(256) void k_approx(int M)
{
    extern __shared__ char sm[];
    const unsigned sbase = (unsigned)__cvta_generic_to_shared(sm);
    const unsigned bB0 = sbase + 131072;          // B buffer 0
    const unsigned bB1 = sbase + 163840;          // B buffer 1 (== ssc start)
    float (*ssc)[132] = (float (*)[132])(sm + 163840);

    const int tid = threadIdx.x;
    const int lane = tid & 31;
    const int warp = tid >> 5;
    const int wm = warp & 3, wn = warp >> 2;
    const int row0 = blockIdx.x * 128;

#pragma unroll
    for (int it = 0; it < 32; ++it) {
        int idx = tid + it * 256;
        int m = idx >> 6, u = idx & 63;
        uint4 v = ((const uint4*)g_hb)[(size_t)(row0 + m) * 64 + u];
        *(uint4*)(sm + m * 1024 + ((u ^ (m & 7)) << 4)) = v;
    }

    float tv[8]; int tix[8];
#pragma unroll
    for (int q = 0; q < 8; ++q) { tv[q] = 3.4e38f; tix[q] = 0; }

    for (int ch = 0; ch < 16; ++ch) {
        const int c0 = ch * 128;
        float d[2][8][4];
#pragma unroll
        for (int i = 0; i < 2; ++i)
#pragma unroll
            for (int j = 0; j < 8; ++j)
#pragma unroll
                for (int q = 0; q < 4; ++q) d[i][j][q] = 0.f;

        auto load_slab = [&](int kbi, unsigned dstoff) {
#pragma unroll
            for (int it = 0; it < 8; ++it) {
                int idx = tid + it * 256;
                int n = idx >> 4, u16 = idx & 15;
                uint4 v = ((const uint4*)g_cbb)[(size_t)(c0 + n) * 64 + kbi * 16 + u16];
                *(uint4*)(sm + dstoff + n * 256 + ((u16 ^ (n & 7)) << 4)) = v;
            }
        };
        auto do_mma = [&](int kbi, unsigned bB) {
#pragma unroll
            for (int s = 0; s < 8; ++s) {
                unsigned a[2][4], b[8][2];
                const int uA = kbi * 16 + s * 2;
#pragma unroll
                for (int i = 0; i < 2; ++i) {
                    int rrow = wm * 32 + i * 16 + ((lane >> 3) & 1) * 8 + (lane & 7);
                    int un = uA + (lane >> 4);
                    unsigned ad = sbase + rrow * 1024 + ((un ^ (rrow & 7)) << 4);
                    LDSM4(a[i][0], a[i][1], a[i][2], a[i][3], ad);
                }
#pragma unroll
                for (int jp = 0; jp < 4; ++jp) {
                    int nr = wn * 64 + jp * 16 + (lane >> 4) * 8 + (lane & 7);
                    int un = s * 2 + ((lane >> 3) & 1);
                    unsigned ad = bB + nr * 256 + ((un ^ (nr & 7)) << 4);
                    LDSM4(b[2 * jp][0], b[2 * jp][1], b[2 * jp + 1][0], b[2 * jp + 1][1], ad);
                }
#pragma unroll
                for (int i = 0; i < 2; ++i)
#pragma unroll
                    for (int j = 0; j < 8; ++j)
                        MMA16816(d[i][j], a[i], b[j]);
            }
        };

        __syncthreads();                 // prev scan done: ssc/B1 and B0 free
        load_slab(0, 131072);
        __syncthreads();                 // B0 ready
        load_slab(1, 163840);            // B1 loads overlap mma(slab0)
        do_mma(0, bB0);
        __syncthreads();                 // B1 ready; B0 free
        load_slab(2, 131072);            // B0 loads overlap mma(slab1)
        do_mma(1, bB1);
        __syncthreads();                 // B0 ready; B1 free
        load_slab(3, 163840);            // B1 loads overlap mma(slab2)
        do_mma(2, bB0);
        __syncthreads();                 // B1 ready
        do_mma(3, bB1);
        __syncthreads();                 // all threads done reading B1

        {
            const int g = lane >> 2, t4 = lane & 3;
#pragma unroll
            for (int i = 0; i < 2; ++i) {
                int rb = wm * 32 + i * 16 + g;
#pragma unroll
                for (int j = 0; j < 8; ++j) {
                    int cw = wn * 64 + j * 8 + t4 * 2;
                    ssc[rb][cw]         = d[i][j][0];
                    ssc[rb][cw + 1]     = d[i][j][1];
                    ssc[rb + 8][cw]     = d[i][j][2];
                    ssc[rb + 8][cw + 1] = d[i][j][3];
                }
            }
        }
        __syncthreads();
        {
            const int srw = tid >> 1, shalf = tid & 1;
#pragma unroll 4
            for (int cc = 0; cc < 64; ++cc) {
                int c = shalf * 64 + cc;
                float s = __fmaf_rn(-2.f, ssc[srw][c], g_cbsq[c0 + c]);
                if (s < tv[7]) {
                    float v = s; int ii = c0 + c;
#pragma unroll
                    for (int q = 0; q < 8; ++q) {
                        if (v < tv[q]) {
                            float tvv = tv[q]; int tii = tix[q];
                            tv[q] = v; tix[q] = ii; v = tvv; ii = tii;
                        }
                    }
                }
            }
        }
    }

    const int srw = tid >> 1, shalf = tid & 1;
#pragma unroll
    for (int q = 0; q < 8; ++q)
        g_cand[(size_t)(row0 + srw) * 16 + shalf * 8 + q] = tix[q];
}

// ---------------------------------------------------------------------------
// Kernel 5: exact rescore (one warp per row) with hsq fused in.
// hsq chain EXACTLY replicates old k_rowsq (lane-strided ascending-j
// __fmaf_rn + shfl_down tree + lane-0 value) on the identical h row values.
// Rescore chain unchanged: sequential ascending-k __fmaf_rn dot;
// dist = fl(fl(hsq-2dot)+cbsq); rank by (dist_bits << 32 | index).
// ---------------------------------------------------------------------------
__global__ __launch_bounds__(256) void k_exact(
    const float* __restrict__ cb, const float* __restrict__ bias,
    float* __restrict__ out, int M)
{
    __shared__ float sh[8][D_IN];
    const int warp = threadIdx.x >> 5, lane = threadIdx.x & 31;
    const int row = blockIdx.x * 8 + warp;
    if (row >= M) return;

    float4* sh4 = (float4*)sh[warp];
    const float4* hrow = (const float4*)(g_h + (size_t)row * D_IN);
#pragma unroll
    for (int i = lane; i < D_IN / 4; i += 32) sh4[i] = hrow[i];
    __syncwarp();

    // hsq: exact k_rowsq chain on the smem copy (same values as g_h)
    float hs;
    {
        const float* p = sh[warp];
        float s = 0.f;
#pragma unroll
        for (int j = 0; j < D_IN / 32; ++j) {
            float v = p[lane + j * 32];
            s = __fmaf_rn(v, v, s);
        }
#pragma unroll
        for (int off = 16; off; off >>= 1)
            s = __fadd_rn(s, __shfl_down_sync(0xffffffffu, s, off));
        hs = __shfl_sync(0xffffffffu, s, 0);
    }

    u64 key = 0xFFFFFFFFFFFFFFFFull;
    if (lane < 16) {
        int c = g_cand[(size_t)row * 16 + lane];
        const float4* crow = (const float4*)(cb + (size_t)c * D_IN);
        float acc = 0.f;
#pragma unroll 8
        for (int i = 0; i < D_IN / 4; ++i) {
            float4 hv = sh4[i];
            float4 cv = crow[i];
            acc = __fmaf_rn(hv.x, cv.x, acc);
            acc = __fmaf_rn(hv.y, cv.y, acc);
            acc = __fmaf_rn(hv.z, cv.z, acc);
            acc = __fmaf_rn(hv.w, cv.w, acc);
        }
        float t = __fmaf_rn(-2.0f, acc, hs);
        float dd = __fadd_rn(t, g_cbsq[c]);
        key = ((u64)__float_as_uint(dd) << 32) | (unsigned)c;
    }
    __syncwarp();

    int cq[4];
#pragma unroll
    for (int q = 0; q < 4; ++q) {
        u64 m = key;
#pragma unroll
        for (int off = 16; off; off >>= 1) {
            u64 o = __shfl_xor_sync(0xffffffffu, m, off);
            if (o < m) m = o;
        }
        cq[q] = (int)(m & 0xFFFFFFFFu);
        if (key == m) key = 0xFFFFFFFFFFFFFFFFull;
    }

#pragma unroll
    for (int j = 0; j < D_OUT / 32; ++j) {
        int col = lane + j * 32;
        float v = bias[col];
#pragma unroll
        for (int q = 0; q < 4; ++q)
            v += g_proj[(size_t)cq[q] * D_OUT + col];
        out[(size_t)row * D_OUT + col] = v;
    }
}

// ---------------------------------------------------------------------------
// Launch
// ---------------------------------------------------------------------------
extern "C" void kernel_launch(void* const* d_in, const int* in_sizes, int n_in,
                              void* d_out, int out_size)
{
    const float* x  = (const float*)d_in[0];   // [M, 512]
    const float* W  = (const float*)d_in[1];   // [512, 512]
    const float* cb = (const float*)d_in[2];   // [2048, 512]
    const float* hw = (const float*)d_in[3];   // [512, 256]
    const float* hb = (const float*)d_in[4];   // [256]
    float* out = (float*)d_out;                // [M, 256]

    const int M = in_sizes[0] / D_IN;
    const int mb2 = (M + 127) / 128;

    const int approx_smem = 131072 + 32768 + 128 * 132 * 4;  // 231424 B
    cudaFuncSetAttribute(k_approx, cudaFuncAttributeMaxDynamicSharedMemorySize,
                         approx_smem);

    k_gemm_xw<<<dim3(mb2, 4), 256>>>(x, W, M);
    k_cbprep<<<NUM_CODES, 256>>>(cb);
    k_proj<<<NUM_CODES / 32, 256>>>(cb, hw);
    k_approx<<<mb2, 256, approx_smem>>>(M);
    k_exact<<<(M + 7) / 8, 256>>>(cb, hb, out, M);
}

// round 17
// speedup vs baseline: 1.1520x; 1.0219x over previous
#include <cuda_runtime.h>
#include <cuda_bf16.h>
#include <cstdint>
#include <cstring>

#define D_IN      512
#define NUM_CODES 2048
#define D_OUT     256
#define MAX_ROWS  100096   // ceil(100000/128)*128

typedef unsigned long long u64;

// Scratch (no allocations allowed -> __device__ globals, zero-initialized)
__device__ float g_h[(size_t)MAX_ROWS * D_IN];            // projected features (exact fp32)
__device__ __nv_bfloat16 g_hb[(size_t)MAX_ROWS * D_IN];   // bf16 copy of h
__device__ __nv_bfloat16 g_cbb[(size_t)NUM_CODES * D_IN]; // bf16 codebook
__device__ float g_proj[(size_t)NUM_CODES * D_OUT];       // 0.25 * codebook @ head_w
__device__ float g_cbsq[NUM_CODES];                       // fl32(||codebook_c||^2)
__device__ int   g_cand[(size_t)MAX_ROWS * 16];           // 16 candidates per row

#define LDSM4(r0,r1,r2,r3,addr) \
    asm volatile("ldmatrix.sync.aligned.m8n8.x4.shared.b16 {%0,%1,%2,%3},[%4];" \
        : "=r"(r0), "=r"(r1), "=r"(r2), "=r"(r3) : "r"(addr))

#define MMA16816(d, a, b) \
    asm volatile("mma.sync.aligned.m16n8k16.row.col.f32.bf16.bf16.f32 " \
        "{%0,%1,%2,%3},{%4,%5,%6,%7},{%8,%9},{%0,%1,%2,%3};" \
        : "+f"((d)[0]), "+f"((d)[1]), "+f"((d)[2]), "+f"((d)[3]) \
        : "r"((a)[0]), "r"((a)[1]), "r"((a)[2]), "r"((a)[3]), "r"((b)[0]), "r"((b)[1]))

__device__ __forceinline__ unsigned bf2u(__nv_bfloat162 v) {
    unsigned u; memcpy(&u, &v, 4); return u;
}

// ---------------------------------------------------------------------------
// Kernel 1: FUSED  h-GEMM  +  codebook prep  +  proj GEMM.
// Blocks with blockIdx.x <  mb : h = x @ linear_proj (exact-bits path,
//   R11-validated 128x128 tile, sequential ascending-k __fmaf_rn chains).
// Blocks with blockIdx.x >= mb : 64 prep CTAs, each owning 32 codes:
//   (a) cb -> bf16 conversion (identical op),
//   (b) cbsq via the EXACT k_rowsq chain (one warp per row, lane-strided
//       ascending-j __fmaf_rn + shfl_down tree 16..1, lane-0 store),
//   (c) proj tile = 0.25 * cb[c0:c0+32] @ head_w (R11 k_proj body verbatim).
// Prep runs concurrently with the GEMM inside one launch (no streams needed).
// ---------------------------------------------------------------------------
__global__ __launch_bounds__(256, 2) void k_gemm_fused(
    const float* __restrict__ A, const float* __restrict__ B,
    const float* __restrict__ cb, const float* __restrict__ hw,
    int M, int mb)
{
    __shared__ float sA[32][132];   // [k][m]   (GEMM path)
    __shared__ float sB[32][132];   // [k][n]   (GEMM path)
    __shared__ float scb[32][64];   //          (prep/proj path)

    const int tid = threadIdx.x;

    if (blockIdx.x >= mb) {
        // ---------------- prep path: 64 CTAs, 32 codes each ----------------
        const int p = (blockIdx.x - mb) * 4 + blockIdx.y;   // 0..63
        const int c0 = p * 32;
        const int lane = tid & 31, warp = tid >> 5;

        // (a) bf16 conversion: 32 rows x 512, 2 elems/thread/iter
        for (int e = tid * 2; e < 32 * D_IN; e += 512) {
            int r = c0 + (e >> 9), k = e & 511;
            float v0 = cb[(size_t)r * D_IN + k];
            float v1 = cb[(size_t)r * D_IN + k + 1];
            *(__nv_bfloat162*)(g_cbb + (size_t)r * D_IN + k) =
                __floats2bfloat162_rn(v0, v1);
        }

        // (b) cbsq: warp w handles rows c0+w*4 .. +3, exact chain per row
#pragma unroll
        for (int rr = 0; rr < 4; ++rr) {
            int r = c0 + warp * 4 + rr;
            const float* pr = cb + (size_t)r * D_IN;
            float s = 0.f;
#pragma unroll
            for (int j = 0; j < D_IN / 32; ++j) {
                float v = pr[lane + j * 32];
                s = __fmaf_rn(v, v, s);
            }
#pragma unroll
            for (int off = 16; off; off >>= 1)
                s = __fadd_rn(s, __shfl_down_sync(0xffffffffu, s, off));
            if (lane == 0) g_cbsq[r] = s;
        }

        // (c) proj tile (R11 k_proj body)
        float acc[32];
#pragma unroll
        for (int r = 0; r < 32; ++r) acc[r] = 0.f;

        for (int kt = 0; kt < D_IN / 64; ++kt) {
            __syncthreads();
#pragma unroll
            for (int i = 0; i < 2; ++i) {
                int e = tid + i * 256;
                int r = e >> 4, k4 = e & 15;
                *(float4*)&scb[r][k4 * 4] =
                    *(const float4*)(cb + (size_t)(c0 + r) * D_IN + kt * 64 + k4 * 4);
            }
            __syncthreads();
#pragma unroll 8
            for (int kk = 0; kk < 64; ++kk) {
                float w = hw[(size_t)(kt * 64 + kk) * D_OUT + tid];
#pragma unroll
                for (int r = 0; r < 32; ++r) acc[r] = __fmaf_rn(scb[r][kk], w, acc[r]);
            }
        }
#pragma unroll
        for (int r = 0; r < 32; ++r)
            g_proj[(size_t)(c0 + r) * D_OUT + tid] = 0.25f * acc[r];
        return;
    }

    // ---------------- GEMM path (unchanged bits) ----------------
    const int tx = tid & 15, ty = tid >> 4;
    const int row0 = blockIdx.x * 128;
    const int col0 = blockIdx.y * 128;

    float acc[8][8];
#pragma unroll
    for (int i = 0; i < 8; ++i)
#pragma unroll
        for (int j = 0; j < 8; ++j) acc[i][j] = 0.f;

    for (int kt = 0; kt < D_IN / 32; ++kt) {   // k tiles ascending
        __syncthreads();
#pragma unroll
        for (int i = 0; i < 4; ++i) {
            int e = tid + i * 256;          // 0..1023
            int r = e >> 3, k4 = e & 7;
            float4 v = make_float4(0.f, 0.f, 0.f, 0.f);
            int gr = row0 + r;
            if (gr < M) v = *(const float4*)(A + (size_t)gr * D_IN + kt * 32 + k4 * 4);
            sA[k4 * 4 + 0][r] = v.x; sA[k4 * 4 + 1][r] = v.y;
            sA[k4 * 4 + 2][r] = v.z; sA[k4 * 4 + 3][r] = v.w;
        }
#pragma unroll
        for (int i = 0; i < 4; ++i) {
            int e = tid + i * 256;          // 0..1023
            int k = e >> 5, n4 = e & 31;
            float4 v = *(const float4*)(B + (size_t)(kt * 32 + k) * D_IN + col0 + n4 * 4);
            *(float4*)&sB[k][n4 * 4] = v;
        }
        __syncthreads();
#pragma unroll
        for (int kk = 0; kk < 32; ++kk) {   // k ascending within tile
            float a[8], b[8];
            *(float4*)&a[0] = *(const float4*)&sA[kk][ty * 8];
            *(float4*)&a[4] = *(const float4*)&sA[kk][ty * 8 + 4];
            *(float4*)&b[0] = *(const float4*)&sB[kk][tx * 8];
            *(float4*)&b[4] = *(const float4*)&sB[kk][tx * 8 + 4];
#pragma unroll
            for (int i = 0; i < 8; ++i)
#pragma unroll
                for (int j = 0; j < 8; ++j)
                    acc[i][j] = __fmaf_rn(a[i], b[j], acc[i][j]);
        }
    }
#pragma unroll
    for (int i = 0; i < 8; ++i) {
        int gr = row0 + ty * 8 + i;
        if (gr < M) {
            float* hp = g_h + (size_t)gr * D_IN + col0 + tx * 8;
            *(float4*)hp       = make_float4(acc[i][0], acc[i][1], acc[i][2], acc[i][3]);
            *(float4*)(hp + 4) = make_float4(acc[i][4], acc[i][5], acc[i][6], acc[i][7]);
            uint4 bb;
            bb.x = bf2u(__floats2bfloat162_rn(acc[i][0], acc[i][1]));
            bb.y = bf2u(__floats2bfloat162_rn(acc[i][2], acc[i][3]));
            bb.z = bf2u(__floats2bfloat162_rn(acc[i][4], acc[i][5]));
            bb.w = bf2u(__floats2bfloat162_rn(acc[i][6], acc[i][7]));
            *(uint4*)(g_hb + (size_t)gr * D_IN + col0 + tx * 8) = bb;
        }
    }
}

// ---------------------------------------------------------------------------
// Kernel 2: approximate distance pass (bf16 HMMA) with software-pipelined B
// (R15-validated). Two 32KB slab buffers; buffer1 overlaid on the score
// region (written only after last MMA of the chunk).
// ---------------------------------------------------------------------------
__global__ __launch_bounds__(256) void k_approx(int M)
{
    extern __shared__ char sm[];
    const unsigned sbase = (unsigned)__cvta_generic_to_shared(sm);
    const unsigned bB0 = sbase + 131072;          // B buffer 0
    const unsigned bB1 = sbase + 163840;          // B buffer 1 (== ssc start)
    float (*ssc)[132] = (float (*)[132])(sm + 163840);

    const int tid = threadIdx.x;
    const int lane = tid & 31;
    const int warp = tid >> 5;
    const int wm = warp & 3, wn = warp >> 2;
    const int row0 = blockIdx.x * 128;

#pragma unroll
    for (int it = 0; it < 32; ++it) {
        int idx = tid + it * 256;
        int m = idx >> 6, u = idx & 63;
        uint4 v = ((const uint4*)g_hb)[(size_t)(row0 + m) * 64 + u];
        *(uint4*)(sm + m * 1024 + ((u ^ (m & 7)) << 4)) = v;
    }

    float tv[8]; int tix[8];
#pragma unroll
    for (int q = 0; q < 8; ++q) { tv[q] = 3.4e38f; tix[q] = 0; }

    for (int ch = 0; ch < 16; ++ch) {
        const int c0 = ch * 128;
        float d[2][8][4];
#pragma unroll
        for (int i = 0; i < 2; ++i)
#pragma unroll
            for (int j = 0; j < 8; ++j)
#pragma unroll
                for (int q = 0; q < 4; ++q) d[i][j][q] = 0.f;

        auto load_slab = [&](int kbi, unsigned dstoff) {
#pragma unroll
            for (int it = 0; it < 8; ++it) {
                int idx = tid + it * 256;
                int n = idx >> 4, u16 = idx & 15;
                uint4 v = ((const uint4*)g_cbb)[(size_t)(c0 + n) * 64 + kbi * 16 + u16];
                *(uint4*)(sm + dstoff + n * 256 + ((u16 ^ (n & 7)) << 4)) = v;
            }
        };
        auto do_mma = [&](int kbi, unsigned bB) {
#pragma unroll
            for (int s = 0; s < 8; ++s) {
                unsigned a[2][4], b[8][2];
                const int uA = kbi * 16 + s * 2;
#pragma unroll
                for (int i = 0; i < 2; ++i) {
                    int rrow = wm * 32 + i * 16 + ((lane >> 3) & 1) * 8 + (lane & 7);
                    int un = uA + (lane >> 4);
                    unsigned ad = sbase + rrow * 1024 + ((un ^ (rrow & 7)) << 4);
                    LDSM4(a[i][0], a[i][1], a[i][2], a[i][3], ad);
                }
#pragma unroll
                for (int jp = 0; jp < 4; ++jp) {
                    int nr = wn * 64 + jp * 16 + (lane >> 4) * 8 + (lane & 7);
                    int un = s * 2 + ((lane >> 3) & 1);
                    unsigned ad = bB + nr * 256 + ((un ^ (nr & 7)) << 4);
                    LDSM4(b[2 * jp][0], b[2 * jp][1], b[2 * jp + 1][0], b[2 * jp + 1][1], ad);
                }
#pragma unroll
                for (int i = 0; i < 2; ++i)
#pragma unroll
                    for (int j = 0; j < 8; ++j)
                        MMA16816(d[i][j], a[i], b[j]);
            }
        };

        __syncthreads();                 // prev scan done: ssc/B1 and B0 free
        load_slab(0, 131072);
        __syncthreads();                 // B0 ready
        load_slab(1, 163840);            // B1 loads overlap mma(slab0)
        do_mma(0, bB0);
        __syncthreads();                 // B1 ready; B0 free
        load_slab(2, 131072);            // B0 loads overlap mma(slab1)
        do_mma(1, bB1);
        __syncthreads();                 // B0 ready; B1 free
        load_slab(3, 163840);            // B1 loads overlap mma(slab2)
        do_mma(2, bB0);
        __syncthreads();                 // B1 ready
        do_mma(3, bB1);
        __syncthreads();                 // all threads done reading B1

        {
            const int g = lane >> 2, t4 = lane & 3;
#pragma unroll
            for (int i = 0; i < 2; ++i) {
                int rb = wm * 32 + i * 16 + g;
#pragma unroll
                for (int j = 0; j < 8; ++j) {
                    int cw = wn * 64 + j * 8 + t4 * 2;
                    ssc[rb][cw]         = d[i][j][0];
                    ssc[rb][cw + 1]     = d[i][j][1];
                    ssc[rb + 8][cw]     = d[i][j][2];
                    ssc[rb + 8][cw + 1] = d[i][j][3];
                }
            }
        }
        __syncthreads();
        {
            const int srw = tid >> 1, shalf = tid & 1;
#pragma unroll 4
            for (int cc = 0; cc < 64; ++cc) {
                int c = shalf * 64 + cc;
                float s = __fmaf_rn(-2.f, ssc[srw][c], g_cbsq[c0 + c]);
                if (s < tv[7]) {
                    float v = s; int ii = c0 + c;
#pragma unroll
                    for (int q = 0; q < 8; ++q) {
                        if (v < tv[q]) {
                            float tvv = tv[q]; int tii = tix[q];
                            tv[q] = v; tix[q] = ii; v = tvv; ii = tii;
                        }
                    }
                }
            }
        }
    }

    const int srw = tid >> 1, shalf = tid & 1;
#pragma unroll
    for (int q = 0; q < 8; ++q)
        g_cand[(size_t)(row0 + srw) * 16 + shalf * 8 + q] = tix[q];
}

// ---------------------------------------------------------------------------
// Kernel 3: exact rescore (one warp per row) with hsq fused in
// (R16-validated). hsq = exact k_rowsq chain on the smem h copy.
// Rescore: sequential ascending-k __fmaf_rn dot; dist = fl(fl(hsq-2dot)+cbsq);
// rank by (dist_bits << 32 | index).
// ---------------------------------------------------------------------------
__global__ __launch_bounds__(256) void k_exact(
    const float* __restrict__ cb, const float* __restrict__ bias,
    float* __restrict__ out, int M)
{
    __shared__ float sh[8][D_IN];
    const int warp = threadIdx.x >> 5, lane = threadIdx.x & 31;
    const int row = blockIdx.x * 8 + warp;
    if (row >= M) return;

    float4* sh4 = (float4*)sh[warp];
    const float4* hrow = (const float4*)(g_h + (size_t)row * D_IN);
#pragma unroll
    for (int i = lane; i < D_IN / 4; i += 32) sh4[i] = hrow[i];
    __syncwarp();

    float hs;
    {
        const float* p = sh[warp];
        float s = 0.f;
#pragma unroll
        for (int j = 0; j < D_IN / 32; ++j) {
            float v = p[lane + j * 32];
            s = __fmaf_rn(v, v, s);
        }
#pragma unroll
        for (int off = 16; off; off >>= 1)
            s = __fadd_rn(s, __shfl_down_sync(0xffffffffu, s, off));
        hs = __shfl_sync(0xffffffffu, s, 0);
    }

    u64 key = 0xFFFFFFFFFFFFFFFFull;
    if (lane < 16) {
        int c = g_cand[(size_t)row * 16 + lane];
        const float4* crow = (const float4*)(cb + (size_t)c * D_IN);
        float acc = 0.f;
#pragma unroll 8
        for (int i = 0; i < D_IN / 4; ++i) {
            float4 hv = sh4[i];
            float4 cv = crow[i];
            acc = __fmaf_rn(hv.x, cv.x, acc);
            acc = __fmaf_rn(hv.y, cv.y, acc);
            acc = __fmaf_rn(hv.z, cv.z, acc);
            acc = __fmaf_rn(hv.w, cv.w, acc);
        }
        float t = __fmaf_rn(-2.0f, acc, hs);
        float dd = __fadd_rn(t, g_cbsq[c]);
        key = ((u64)__float_as_uint(dd) << 32) | (unsigned)c;
    }
    __syncwarp();

    int cq[4];
#pragma unroll
    for (int q = 0; q < 4; ++q) {
        u64 m = key;
#pragma unroll
        for (int off = 16; off; off >>= 1) {
            u64 o = __shfl_xor_sync(0xffffffffu, m, off);
            if (o < m) m = o;
        }
        cq[q] = (int)(m & 0xFFFFFFFFu);
        if (key == m) key = 0xFFFFFFFFFFFFFFFFull;
    }

#pragma unroll
    for (int j = 0; j < D_OUT / 32; ++j) {
        int col = lane + j * 32;
        float v = bias[col];
#pragma unroll
        for (int q = 0; q < 4; ++q)
            v += g_proj[(size_t)cq[q] * D_OUT + col];
        out[(size_t)row * D_OUT + col] = v;
    }
}

// ---------------------------------------------------------------------------
// Launch
// ---------------------------------------------------------------------------
extern "C" void kernel_launch(void* const* d_in, const int* in_sizes, int n_in,
                              void* d_out, int out_size)
{
    const float* x  = (const float*)d_in[0];   // [M, 512]
    const float* W  = (const float*)d_in[1];   // [512, 512]
    const float* cb = (const float*)d_in[2];   // [2048, 512]
    const float* hw = (const float*)d_in[3];   // [512, 256]
    const float* hb = (const float*)d_in[4];   // [256]
    float* out = (float*)d_out;                // [M, 256]

    const int M = in_sizes[0] / D_IN;
    const int mb2 = (M + 127) / 128;

    const int approx_smem = 131072 + 32768 + 128 * 132 * 4;  // 231424 B
    cudaFuncSetAttribute(k_approx, cudaFuncAttributeMaxDynamicSharedMemorySize,
                         approx_smem);

    // grid.x = mb2 GEMM columns + 16 prep columns (x 4 y-slices = 64 prep CTAs)
    k_gemm_fused<<<dim3(mb2 + 16, 4), 256>>>(x, W, cb, hw, M, mb2);
    k_approx<<<mb2, 256, approx_smem>>>(M);
    k_exact<<<(M + 7) / 8, 256>>>(cb, hb, out, M);
}